// round 10
// baseline (speedup 1.0000x reference)
#include <cuda_runtime.h>
#include <cuda_fp16.h>
#include <cstdint>

// ---------------- problem constants ----------------
static constexpr int BB  = 8;
static constexpr int LL  = 4096;
static constexpr int HH  = 16;
static constexpr int DHD = 64;
static constexpr int MM  = BB * LL;       // 32768 rows

// ---------------- scratch (device globals; no allocation allowed) ----------------
__device__ __half g_Xp  [33554432];   // MM*1024 : X + pe (fp16)
__device__ __half g_qkv [100663296];  // MM*3072 : packed q|k|v (fp16)
__device__ __half g_ctx [33554432];   // MM*1024 : attention context (fp16)
__device__ __half g_T   [33554432];   // MM*1024 : O-proj output (fp16)
__device__ __half g_Y   [33554432];   // MM*1024 : LN1 output (fp16)
__device__ __half g_Hb  [134217728];  // MM*4096 : relu(FFN1) (fp16)
__device__ __half g_Z   [33554432];   // MM*1024 : FFN2 output (fp16)
__device__ __half g_Wqkv[3145728];    // [3072][1024]  transposed q|k|v weights
__device__ float  g_bqkv[3072];
__device__ __half g_Wo  [1048576];    // [1024][1024]  transposed
__device__ __half g_W1  [4194304];    // [4096][1024]  transposed
__device__ __half g_W2  [4194304];    // [1024][4096]  transposed
__device__ float  g_pad [32];         // dummy-kernel target

// ---------------- helpers ----------------
__device__ __forceinline__ unsigned smem_u32(const void* p) {
    return (unsigned)__cvta_generic_to_shared(p);
}
__device__ __forceinline__ void cp16(unsigned s, const void* g) {
    asm volatile("cp.async.cg.shared.global [%0], [%1], 16;" :: "r"(s), "l"(g));
}
__device__ __forceinline__ void cp_commit() { asm volatile("cp.async.commit_group;"); }
__device__ __forceinline__ void cp_wait1()  { asm volatile("cp.async.wait_group 1;"); }
__device__ __forceinline__ void ldsm4(unsigned& r0, unsigned& r1, unsigned& r2, unsigned& r3,
                                      unsigned addr) {
    asm volatile("ldmatrix.sync.aligned.m8n8.x4.shared.b16 {%0,%1,%2,%3}, [%4];"
                 : "=r"(r0), "=r"(r1), "=r"(r2), "=r"(r3) : "r"(addr));
}

// ---------------- prep: Xp = fp16(X + pe) ----------------
__global__ void prep_kernel(const float* __restrict__ X, const float* __restrict__ pe,
                            __half* __restrict__ Xp) {
    long i = ((long)blockIdx.x * blockDim.x + threadIdx.x) * 4;
    float4 x = *(const float4*)(X + i);
    long pi = i & (4194304L - 1);
    float4 p = *(const float4*)(pe + pi);
    __half2 h0 = __floats2half2_rn(x.x + p.x, x.y + p.y);
    __half2 h1 = __floats2half2_rn(x.z + p.z, x.w + p.w);
    *(__half2*)(Xp + i)     = h0;
    *(__half2*)(Xp + i + 2) = h1;
}

// ---------------- dummy (slot alignment so ncu profiles the QKV GEMM) -------------
__global__ void dummy_kernel(float* __restrict__ p) {
    if (threadIdx.x == 0) p[blockIdx.x] = 0.f;
}

// ---------------- fused weight prep: 6 transposes + bias pack in one launch -------
__device__ __forceinline__ void transpose_tile(const float* __restrict__ src,
                                               __half* __restrict__ dst,
                                               int K, int N, int tx, int ty,
                                               int x, int y) {
    __shared__ float t[32][33];
    const int n0 = tx * 32, k0 = ty * 32;
#pragma unroll
    for (int j = 0; j < 32; j += 8)
        t[y + j][x] = src[(long)(k0 + y + j) * N + n0 + x];
    __syncthreads();
#pragma unroll
    for (int j = 0; j < 32; j += 8)
        dst[(long)(n0 + y + j) * K + k0 + x] = __float2half_rn(t[x][y + j]);
}

__global__ void prep_weights(const float* __restrict__ Wq, const float* __restrict__ Wk,
                             const float* __restrict__ Wv, const float* __restrict__ Wo,
                             const float* __restrict__ W1, const float* __restrict__ W2,
                             const float* __restrict__ bq, const float* __restrict__ bk,
                             const float* __restrict__ bv,
                             __half* __restrict__ Wqkv, __half* __restrict__ WoT,
                             __half* __restrict__ W1T, __half* __restrict__ W2T,
                             float* __restrict__ bqkv) {
    const int id = blockIdx.x;
    const int x = threadIdx.x, y = threadIdx.y;
    if (id < 1024) {
        transpose_tile(Wq, Wqkv + 0, 1024, 1024, id & 31, id >> 5, x, y);
    } else if (id < 2048) {
        transpose_tile(Wk, Wqkv + 1048576, 1024, 1024, (id - 1024) & 31, (id - 1024) >> 5, x, y);
    } else if (id < 3072) {
        transpose_tile(Wv, Wqkv + 2097152, 1024, 1024, (id - 2048) & 31, (id - 2048) >> 5, x, y);
    } else if (id < 4096) {
        transpose_tile(Wo, WoT, 1024, 1024, (id - 3072) & 31, (id - 3072) >> 5, x, y);
    } else if (id < 8192) {
        int l = id - 4096;
        transpose_tile(W1, W1T, 1024, 4096, l & 127, l >> 7, x, y);
    } else if (id < 12288) {
        int l = id - 8192;
        transpose_tile(W2, W2T, 4096, 1024, l & 31, l >> 5, x, y);
    } else {
        int i = (id - 12288) * 256 + y * 32 + x;
        const float* src = (i < 1024) ? bq : ((i < 2048) ? bk : bv);
        bqkv[i] = src[i & 1023];
    }
}

// ---------------- GEMM: fp16 mma.sync m16n8k16 + ldmatrix ----------------
// 128x256x32 CTA tile, 8 warps (2m x 4n) each 64x64, 3-stage cp.async
static constexpr int GBM = 128, GBN = 256, GBK = 32, STAGES = 3;
static constexpr int S_STRIDE = 40;                  // halves; 80B row (conflict-free)
static constexpr int SA_SIZE = GBM * S_STRIDE;       // 5120 halves
static constexpr int SB_SIZE = GBN * S_STRIDE;       // 10240 halves
static constexpr int STG_SIZE = SA_SIZE + SB_SIZE;   // 15360 halves = 30720 B
static constexpr int GEMM_SMEM = STAGES * STG_SIZE * 2;   // 92160 B

// mode: 0 = fp32 store, 1 = fp16 store, 2 = relu + fp16 store
template <int KT>
__global__ __launch_bounds__(256, 1)
void gemm_fp16(const __half* __restrict__ A, const __half* __restrict__ Bt,
               const float* __restrict__ bias, void* __restrict__ Cv,
               int M, int N, int mode) {
    constexpr int K = KT * GBK;
    extern __shared__ __half smem[];
    const int tid  = threadIdx.x;
    const int bm   = blockIdx.y * GBM, bn = blockIdx.x * GBN;
    const int warp = tid >> 5, lane = tid & 31;
    const int wm   = (warp >> 2) * 64, wn = (warp & 3) * 64;
    const int g    = lane >> 2, tg = lane & 3;

    const int a_row = (wm + (lane & 15)) * S_STRIDE + (lane >> 4) * 8;
    const int b_row = (wn + ((lane >> 4) & 1) * 8 + (lane & 7)) * S_STRIDE
                    + ((lane >> 3) & 1) * 8;

    float c[4][8][4];
#pragma unroll
    for (int mt = 0; mt < 4; mt++)
#pragma unroll
        for (int nt = 0; nt < 8; nt++)
#pragma unroll
            for (int j = 0; j < 4; j++) c[mt][nt][j] = 0.f;

    auto load_stage = [&](int stg, int kt) {
        __half* sA = smem + stg * STG_SIZE;
        __half* sB = sA + SA_SIZE;
        const __half* Ag = A + (long)bm * K + (long)kt * GBK;
        const __half* Bg = Bt + (long)bn * K + (long)kt * GBK;
#pragma unroll
        for (int i = 0; i < 2; i++) {
            int idx = i * 256 + tid;          // 0..511
            int row = idx >> 2;               // 0..127
            int cb  = (idx & 3) * 8;
            cp16(smem_u32(sA + row * S_STRIDE + cb), Ag + (long)row * K + cb);
        }
#pragma unroll
        for (int i = 0; i < 4; i++) {
            int idx = i * 256 + tid;          // 0..1023
            int row = idx >> 2;               // 0..255
            int cb  = (idx & 3) * 8;
            cp16(smem_u32(sB + row * S_STRIDE + cb), Bg + (long)row * K + cb);
        }
        cp_commit();
    };

    load_stage(0, 0);
    load_stage(1, 1);

#pragma unroll 1
    for (int kt = 0; kt < KT; kt++) {
        cp_wait1();
        __syncthreads();
        if (kt + 2 < KT) load_stage((kt + 2) % STAGES, kt + 2);
        else             cp_commit();

        const unsigned sAu = smem_u32(smem + (kt % STAGES) * STG_SIZE);
        const unsigned sBu = sAu + SA_SIZE * 2;
#pragma unroll
        for (int kk = 0; kk < 2; kk++) {
            const int k0 = kk * 16;
            unsigned a[4][4], b[8][2];
#pragma unroll
            for (int mt = 0; mt < 4; mt++)
                ldsm4(a[mt][0], a[mt][1], a[mt][2], a[mt][3],
                      sAu + 2u * (a_row + mt * 16 * S_STRIDE + k0));
#pragma unroll
            for (int np = 0; np < 4; np++)
                ldsm4(b[2 * np][0], b[2 * np][1], b[2 * np + 1][0], b[2 * np + 1][1],
                      sBu + 2u * (b_row + np * 16 * S_STRIDE + k0));
#pragma unroll
            for (int mt = 0; mt < 4; mt++)
#pragma unroll
                for (int nt = 0; nt < 8; nt++) {
                    asm volatile(
                        "mma.sync.aligned.m16n8k16.row.col.f32.f16.f16.f32 "
                        "{%0,%1,%2,%3},{%4,%5,%6,%7},{%8,%9},{%0,%1,%2,%3};"
                        : "+f"(c[mt][nt][0]), "+f"(c[mt][nt][1]),
                          "+f"(c[mt][nt][2]), "+f"(c[mt][nt][3])
                        : "r"(a[mt][0]), "r"(a[mt][1]), "r"(a[mt][2]), "r"(a[mt][3]),
                          "r"(b[nt][0]), "r"(b[nt][1]));
                }
        }
    }

    float* Cf = (float*)Cv;
    __half* Ch = (__half*)Cv;
#pragma unroll
    for (int mt = 0; mt < 4; mt++) {
        const int r0 = bm + wm + mt * 16 + g;
#pragma unroll
        for (int nt = 0; nt < 8; nt++) {
            const int col = bn + wn + nt * 8 + tg * 2;
            const float b0 = bias[col], b1 = bias[col + 1];
            float v0 = c[mt][nt][0] + b0, v1 = c[mt][nt][1] + b1;
            float v2 = c[mt][nt][2] + b0, v3 = c[mt][nt][3] + b1;
            if (mode == 2) {
                v0 = fmaxf(v0, 0.f); v1 = fmaxf(v1, 0.f);
                v2 = fmaxf(v2, 0.f); v3 = fmaxf(v3, 0.f);
            }
            if (mode >= 1) {
                *(__half2*)&Ch[(long)r0 * N + col]       = __floats2half2_rn(v0, v1);
                *(__half2*)&Ch[(long)(r0 + 8) * N + col] = __floats2half2_rn(v2, v3);
            } else {
                *(float2*)&Cf[(long)r0 * N + col]       = make_float2(v0, v1);
                *(float2*)&Cf[(long)(r0 + 8) * N + col] = make_float2(v2, v3);
            }
        }
    }
}

// ---------------- window-3 attention: one warp per (b,l), all 16 heads ------------
__global__ __launch_bounds__(128)
void attn_kernel(const __half* __restrict__ qkv,
                 const unsigned char* __restrict__ mask,
                 __half* __restrict__ ctx) {
    const int wg   = (blockIdx.x * blockDim.x + threadIdx.x) >> 5;  // = b*L + l
    const int lane = threadIdx.x & 31;
    const int l = wg & (LL - 1);
    const int b = wg >> 12;

    uint4 qv[4];
    const uint4* qp = (const uint4*)(qkv + (long)wg * 3072 + lane * 32);
#pragma unroll
    for (int i = 0; i < 4; i++) qv[i] = qp[i];
    float qf[32];
#pragma unroll
    for (int i = 0; i < 4; i++) {
        const __half2* h = (const __half2*)&qv[i];
#pragma unroll
        for (int j = 0; j < 4; j++) {
            float2 f = __half22float2(h[j]);
            qf[i * 8 + 2 * j]     = f.x;
            qf[i * 8 + 2 * j + 1] = f.y;
        }
    }

    float s[3];
    bool allow[3];
    int krow[3];
#pragma unroll
    for (int w = 0; w < 3; w++) {
        int idx = l - 1 + w;
        bool valid = (idx >= 0) && (idx < LL);
        int idxc = min(max(idx, 0), LL - 1);
        krow[w] = (b << 12) + idxc;
        const uint4* kp = (const uint4*)(qkv + (long)krow[w] * 3072 + 1024 + lane * 32);
        float a0 = 0.f, a1 = 0.f;
#pragma unroll
        for (int i = 0; i < 4; i++) {
            uint4 kvv = kp[i];
            const __half2* h = (const __half2*)&kvv;
#pragma unroll
            for (int j = 0; j < 4; j++) {
                float2 f = __half22float2(h[j]);
                a0 = fmaf(qf[i * 8 + 2 * j],     f.x, a0);
                a1 = fmaf(qf[i * 8 + 2 * j + 1], f.y, a1);
            }
        }
        float sv = a0 + a1;
        sv += __shfl_xor_sync(0xffffffffu, sv, 1);
        s[w] = sv;
        allow[w] = valid && (mask[krow[w]] == 0);
    }

#pragma unroll
    for (int w = 0; w < 3; w++) s[w] = allow[w] ? s[w] * 0.125f : -1e30f;
    float m = fmaxf(s[0], fmaxf(s[1], s[2]));
    float e0 = __expf(s[0] - m), e1 = __expf(s[1] - m), e2 = __expf(s[2] - m);
    float inv = 1.f / (e0 + e1 + e2);
    __half2 p[3];
    p[0] = __float2half2_rn(e0 * inv);
    p[1] = __float2half2_rn(e1 * inv);
    p[2] = __float2half2_rn(e2 * inv);

    __half2 o[16];
#pragma unroll
    for (int i = 0; i < 16; i++) o[i] = __float2half2_rn(0.f);
#pragma unroll
    for (int w = 0; w < 3; w++) {
        const uint4* vp = (const uint4*)(qkv + (long)krow[w] * 3072 + 2048 + lane * 32);
#pragma unroll
        for (int i = 0; i < 4; i++) {
            uint4 vv = vp[i];
            const __half2* h = (const __half2*)&vv;
#pragma unroll
            for (int j = 0; j < 4; j++)
                o[i * 4 + j] = __hfma2(p[w], h[j], o[i * 4 + j]);
        }
    }

    uint4* op = (uint4*)(ctx + (long)wg * 1024 + lane * 32);
#pragma unroll
    for (int i = 0; i < 4; i++) {
        uint4 v;
        v.x = *(unsigned*)&o[i * 4 + 0];
        v.y = *(unsigned*)&o[i * 4 + 1];
        v.z = *(unsigned*)&o[i * 4 + 2];
        v.w = *(unsigned*)&o[i * 4 + 3];
        op[i] = v;
    }
}

// ---------------- residual + layernorm: both inputs fp16 ----------------
template <int OUTH>
__global__ void resln_kernel(const __half* __restrict__ Xr, const __half* __restrict__ Yr,
                             const float* __restrict__ gamma, const float* __restrict__ beta,
                             void* __restrict__ outv) {
    const int row = blockIdx.x;
    const int tid = threadIdx.x;
    const int lane = tid & 31, warp = tid >> 5;

    __half2 xh0 = ((const __half2*)(Xr + (long)row * 1024))[2 * tid];
    __half2 xh1 = ((const __half2*)(Xr + (long)row * 1024))[2 * tid + 1];
    __half2 yh0 = ((const __half2*)(Yr + (long)row * 1024))[2 * tid];
    __half2 yh1 = ((const __half2*)(Yr + (long)row * 1024))[2 * tid + 1];
    float2 x0 = __half22float2(xh0), x1 = __half22float2(xh1);
    float2 y0 = __half22float2(yh0), y1 = __half22float2(yh1);
    float v0 = x0.x + y0.x, v1 = x0.y + y0.y, v2 = x1.x + y1.x, v3 = x1.y + y1.y;
    float s  = v0 + v1 + v2 + v3;
    float ss = v0 * v0 + v1 * v1 + v2 * v2 + v3 * v3;
#pragma unroll
    for (int off = 16; off; off >>= 1) {
        s  += __shfl_xor_sync(0xffffffffu, s, off);
        ss += __shfl_xor_sync(0xffffffffu, ss, off);
    }
    __shared__ float rs[8], rss[8];
    __shared__ float mean_s, rstd_s;
    if (lane == 0) { rs[warp] = s; rss[warp] = ss; }
    __syncthreads();
    if (tid == 0) {
        float S = 0.f, SS = 0.f;
#pragma unroll
        for (int i = 0; i < 8; i++) { S += rs[i]; SS += rss[i]; }
        float m = S * (1.f / 1024.f);
        float var = SS * (1.f / 1024.f) - m * m;
        mean_s = m;
        rstd_s = rsqrtf(var + 1e-5f);
    }
    __syncthreads();
    const float m = mean_s, r = rstd_s;
    float4 gm = ((const float4*)gamma)[tid];
    float4 bt = ((const float4*)beta)[tid];
    float o0 = (v0 - m) * r * gm.x + bt.x;
    float o1 = (v1 - m) * r * gm.y + bt.y;
    float o2 = (v2 - m) * r * gm.z + bt.z;
    float o3 = (v3 - m) * r * gm.w + bt.w;
    if (OUTH) {
        __half* out = (__half*)outv;
        ((__half2*)(out + (long)row * 1024))[2 * tid]     = __floats2half2_rn(o0, o1);
        ((__half2*)(out + (long)row * 1024))[2 * tid + 1] = __floats2half2_rn(o2, o3);
    } else {
        float* out = (float*)outv;
        ((float4*)(out + (long)row * 1024))[tid] = make_float4(o0, o1, o2, o3);
    }
}

// ---------------- launch ----------------
extern "C" void kernel_launch(void* const* d_in, const int* in_sizes, int n_in,
                              void* d_out, int out_size) {
    const float* X  = (const float*)d_in[0];
    const unsigned char* mask = (const unsigned char*)d_in[1];
    const float* pe = (const float*)d_in[2];
    const float* Wq = (const float*)d_in[3];
    const float* Wk = (const float*)d_in[4];
    const float* Wv = (const float*)d_in[5];
    const float* bq = (const float*)d_in[6];
    const float* bk = (const float*)d_in[7];
    const float* bv = (const float*)d_in[8];
    const float* Wo = (const float*)d_in[9];
    const float* bo = (const float*)d_in[10];
    const float* g1 = (const float*)d_in[11];
    const float* be1 = (const float*)d_in[12];
    const float* W1 = (const float*)d_in[13];
    const float* b1 = (const float*)d_in[14];
    const float* W2 = (const float*)d_in[15];
    const float* b2 = (const float*)d_in[16];
    const float* g2 = (const float*)d_in[17];
    const float* be2 = (const float*)d_in[18];
    float* out = (float*)d_out;

    void *pXp, *pqkv, *pctx, *pT, *pY, *pHb, *pZ, *pWqkv, *pbqkv, *pWo, *pW1, *pW2, *pPad;
    cudaGetSymbolAddress(&pXp, g_Xp);
    cudaGetSymbolAddress(&pqkv, g_qkv);
    cudaGetSymbolAddress(&pctx, g_ctx);
    cudaGetSymbolAddress(&pT, g_T);
    cudaGetSymbolAddress(&pY, g_Y);
    cudaGetSymbolAddress(&pHb, g_Hb);
    cudaGetSymbolAddress(&pZ, g_Z);
    cudaGetSymbolAddress(&pWqkv, g_Wqkv);
    cudaGetSymbolAddress(&pbqkv, g_bqkv);
    cudaGetSymbolAddress(&pWo, g_Wo);
    cudaGetSymbolAddress(&pW1, g_W1);
    cudaGetSymbolAddress(&pW2, g_W2);
    cudaGetSymbolAddress(&pPad, g_pad);
    __half* Xp   = (__half*)pXp;   __half* qkv  = (__half*)pqkv;
    __half* ctx  = (__half*)pctx;  __half* T    = (__half*)pT;
    __half* Y    = (__half*)pY;    __half* Hb   = (__half*)pHb;
    __half* Z    = (__half*)pZ;    __half* Wqkv = (__half*)pWqkv;
    float*  bqkv = (float*)pbqkv;  __half* WoT  = (__half*)pWo;
    __half* W1T  = (__half*)pW1;   __half* W2T  = (__half*)pW2;

    cudaFuncSetAttribute(gemm_fp16<32>,  cudaFuncAttributeMaxDynamicSharedMemorySize, GEMM_SMEM);
    cudaFuncSetAttribute(gemm_fp16<128>, cudaFuncAttributeMaxDynamicSharedMemorySize, GEMM_SMEM);

    // 1. prep X+pe
    prep_kernel<<<32768, 256>>>(X, pe, Xp);
    // 2. all weight transposes + bias pack
    prep_weights<<<12300, dim3(32, 8)>>>(Wq, Wk, Wv, Wo, W1, W2, bq, bk, bv,
                                         Wqkv, WoT, W1T, W2T, bqkv);
    // 3. dummy (aligns QKV GEMM into the profiled launch slot)
    dummy_kernel<<<1, 32>>>((float*)pPad);

    // 4. QKV projection  [32768,1024] x [1024,3072]
    gemm_fp16<32><<<dim3(12, 256), 256, GEMM_SMEM>>>(Xp, Wqkv, bqkv, qkv, MM, 3072, 1);

    // 5. window-3 attention (warp per (b,l))
    attn_kernel<<<8192, 128>>>(qkv, mask, ctx);

    // 6. O projection -> T (fp16)
    gemm_fp16<32><<<dim3(4, 256), 256, GEMM_SMEM>>>(ctx, WoT, bo, T, MM, 1024, 1);

    // 7. LN1(Xp + T) -> Y (fp16)
    resln_kernel<1><<<32768, 256>>>(Xp, T, g1, be1, Y);

    // 8. FFN1: relu(Y @ W1 + b1) -> Hb (fp16)
    gemm_fp16<32><<<dim3(16, 256), 256, GEMM_SMEM>>>(Y, W1T, b1, Hb, MM, 4096, 2);

    // 9. FFN2: Hb @ W2 + b2 -> Z (fp16)
    gemm_fp16<128><<<dim3(4, 256), 256, GEMM_SMEM>>>(Hb, W2T, b2, Z, MM, 1024, 1);

    // 10. LN2(Y + Z) -> out (fp32)
    resln_kernel<0><<<32768, 256>>>(Y, Z, g2, be2, out);
}

// round 13
// speedup vs baseline: 1.1417x; 1.1417x over previous
#include <cuda_runtime.h>
#include <cuda_fp16.h>
#include <cstdint>

// ---------------- problem constants ----------------
static constexpr int BB  = 8;
static constexpr int LL  = 4096;
static constexpr int HH  = 16;
static constexpr int DHD = 64;
static constexpr int MM  = BB * LL;       // 32768 rows

// ---------------- scratch (device globals; no allocation allowed) ----------------
__device__ __half g_Xp  [33554432];   // MM*1024 : X + pe (fp16)
__device__ __half g_qkv [100663296];  // MM*3072 : packed q|k|v (fp16)
__device__ __half g_ctx [33554432];   // MM*1024 : attention context (fp16)
__device__ __half g_T   [33554432];   // MM*1024 : O-proj output (fp16)
__device__ __half g_Y   [33554432];   // MM*1024 : LN1 output (fp16)
__device__ __half g_Hb  [134217728];  // MM*4096 : relu(FFN1) (fp16)
__device__ __half g_Z   [33554432];   // MM*1024 : FFN2 output (fp16)
__device__ __half g_Wqkv[3145728];    // [3072][1024]  transposed q|k|v weights
__device__ float  g_bqkv[3072];
__device__ __half g_Wo  [1048576];    // [1024][1024]  transposed
__device__ __half g_W1  [4194304];    // [4096][1024]  transposed
__device__ __half g_W2  [4194304];    // [1024][4096]  transposed
__device__ float  g_pad [32];         // dummy-kernel target

// ---------------- helpers ----------------
__device__ __forceinline__ unsigned smem_u32(const void* p) {
    return (unsigned)__cvta_generic_to_shared(p);
}
__device__ __forceinline__ void cp16(unsigned s, const void* g) {
    asm volatile("cp.async.cg.shared.global [%0], [%1], 16;" :: "r"(s), "l"(g));
}
__device__ __forceinline__ void cp_commit() { asm volatile("cp.async.commit_group;"); }
__device__ __forceinline__ void cp_wait1()  { asm volatile("cp.async.wait_group 1;"); }
__device__ __forceinline__ void ldsm4(unsigned& r0, unsigned& r1, unsigned& r2, unsigned& r3,
                                      unsigned addr) {
    asm volatile("ldmatrix.sync.aligned.m8n8.x4.shared.b16 {%0,%1,%2,%3}, [%4];"
                 : "=r"(r0), "=r"(r1), "=r"(r2), "=r"(r3) : "r"(addr));
}

// ---------------- prep: Xp = fp16(X + pe) ----------------
__global__ void prep_kernel(const float* __restrict__ X, const float* __restrict__ pe,
                            __half* __restrict__ Xp) {
    long i = ((long)blockIdx.x * blockDim.x + threadIdx.x) * 4;
    float4 x = *(const float4*)(X + i);
    long pi = i & (4194304L - 1);
    float4 p = *(const float4*)(pe + pi);
    __half2 h0 = __floats2half2_rn(x.x + p.x, x.y + p.y);
    __half2 h1 = __floats2half2_rn(x.z + p.z, x.w + p.w);
    *(__half2*)(Xp + i)     = h0;
    *(__half2*)(Xp + i + 2) = h1;
}

// ---------------- dummy (slot alignment so ncu profiles the QKV GEMM) -------------
__global__ void dummy_kernel(float* __restrict__ p) {
    if (threadIdx.x == 0) p[blockIdx.x] = 0.f;
}

// ---------------- fused weight prep: 6 transposes + bias pack in one launch -------
__device__ __forceinline__ void transpose_tile(const float* __restrict__ src,
                                               __half* __restrict__ dst,
                                               int K, int N, int tx, int ty,
                                               int x, int y) {
    __shared__ float t[32][33];
    const int n0 = tx * 32, k0 = ty * 32;
#pragma unroll
    for (int j = 0; j < 32; j += 8)
        t[y + j][x] = src[(long)(k0 + y + j) * N + n0 + x];
    __syncthreads();
#pragma unroll
    for (int j = 0; j < 32; j += 8)
        dst[(long)(n0 + y + j) * K + k0 + x] = __float2half_rn(t[x][y + j]);
}

__global__ void prep_weights(const float* __restrict__ Wq, const float* __restrict__ Wk,
                             const float* __restrict__ Wv, const float* __restrict__ Wo,
                             const float* __restrict__ W1, const float* __restrict__ W2,
                             const float* __restrict__ bq, const float* __restrict__ bk,
                             const float* __restrict__ bv,
                             __half* __restrict__ Wqkv, __half* __restrict__ WoT,
                             __half* __restrict__ W1T, __half* __restrict__ W2T,
                             float* __restrict__ bqkv) {
    const int id = blockIdx.x;
    const int x = threadIdx.x, y = threadIdx.y;
    if (id < 1024) {
        transpose_tile(Wq, Wqkv + 0, 1024, 1024, id & 31, id >> 5, x, y);
    } else if (id < 2048) {
        transpose_tile(Wk, Wqkv + 1048576, 1024, 1024, (id - 1024) & 31, (id - 1024) >> 5, x, y);
    } else if (id < 3072) {
        transpose_tile(Wv, Wqkv + 2097152, 1024, 1024, (id - 2048) & 31, (id - 2048) >> 5, x, y);
    } else if (id < 4096) {
        transpose_tile(Wo, WoT, 1024, 1024, (id - 3072) & 31, (id - 3072) >> 5, x, y);
    } else if (id < 8192) {
        int l = id - 4096;
        transpose_tile(W1, W1T, 1024, 4096, l & 127, l >> 7, x, y);
    } else if (id < 12288) {
        int l = id - 8192;
        transpose_tile(W2, W2T, 4096, 1024, l & 31, l >> 5, x, y);
    } else {
        int i = (id - 12288) * 256 + y * 32 + x;
        const float* src = (i < 1024) ? bq : ((i < 2048) ? bk : bv);
        bqkv[i] = src[i & 1023];
    }
}

// ---------------- GEMM: fp16 mma.sync m16n8k16 + ldmatrix ----------------
// 128x128x32 CTA tile, 8 warps (4m x 2n) each 32x64, 3-stage cp.async, 2 CTA/SM
static constexpr int GBM = 128, GBN = 128, GBK = 32, STAGES = 3;
static constexpr int S_STRIDE = 40;                  // halves; 80B row (conflict-free)
static constexpr int SA_SIZE = GBM * S_STRIDE;
static constexpr int SB_SIZE = GBN * S_STRIDE;
static constexpr int STG_SIZE = SA_SIZE + SB_SIZE;   // 10240 halves = 20480 B
static constexpr int GEMM_SMEM = STAGES * STG_SIZE * 2;   // 61440 B

// mode: 0 = fp32 store, 1 = fp16 store, 2 = relu + fp16 store
template <int KT>
__global__ __launch_bounds__(256, 2)
void gemm_fp16(const __half* __restrict__ A, const __half* __restrict__ Bt,
               const float* __restrict__ bias, void* __restrict__ Cv,
               int M, int N, int mode) {
    constexpr int K = KT * GBK;
    extern __shared__ __half smem[];
    const int tid  = threadIdx.x;
    const int bm   = blockIdx.y * GBM, bn = blockIdx.x * GBN;
    const int warp = tid >> 5, lane = tid & 31;
    const int wm   = (warp >> 1) * 32, wn = (warp & 1) * 64;
    const int g    = lane >> 2, tg = lane & 3;

    const int a_row = (wm + (lane & 15)) * S_STRIDE + (lane >> 4) * 8;
    const int b_row = (wn + ((lane >> 4) & 1) * 8 + (lane & 7)) * S_STRIDE
                    + ((lane >> 3) & 1) * 8;

    float c[2][8][4];
#pragma unroll
    for (int mt = 0; mt < 2; mt++)
#pragma unroll
        for (int nt = 0; nt < 8; nt++)
#pragma unroll
            for (int j = 0; j < 4; j++) c[mt][nt][j] = 0.f;

    auto load_stage = [&](int stg, int kt) {
        __half* sA = smem + stg * STG_SIZE;
        __half* sB = sA + SA_SIZE;
        const __half* Ag = A + (long)bm * K + (long)kt * GBK;
        const __half* Bg = Bt + (long)bn * K + (long)kt * GBK;
#pragma unroll
        for (int i = 0; i < 2; i++) {
            int idx = i * 256 + tid;          // 0..511
            int row = idx >> 2;               // 0..127
            int cb  = (idx & 3) * 8;
            cp16(smem_u32(sA + row * S_STRIDE + cb), Ag + (long)row * K + cb);
        }
#pragma unroll
        for (int i = 0; i < 2; i++) {
            int idx = i * 256 + tid;
            int row = idx >> 2;
            int cb  = (idx & 3) * 8;
            cp16(smem_u32(sB + row * S_STRIDE + cb), Bg + (long)row * K + cb);
        }
        cp_commit();
    };

    load_stage(0, 0);
    load_stage(1, 1);

#pragma unroll 1
    for (int kt = 0; kt < KT; kt++) {
        cp_wait1();
        __syncthreads();
        if (kt + 2 < KT) load_stage((kt + 2) % STAGES, kt + 2);
        else             cp_commit();

        const unsigned sAu = smem_u32(smem + (kt % STAGES) * STG_SIZE);
        const unsigned sBu = sAu + SA_SIZE * 2;
#pragma unroll
        for (int kk = 0; kk < 2; kk++) {
            const int k0 = kk * 16;
            unsigned a[2][4], b[8][2];
#pragma unroll
            for (int mt = 0; mt < 2; mt++)
                ldsm4(a[mt][0], a[mt][1], a[mt][2], a[mt][3],
                      sAu + 2u * (a_row + mt * 16 * S_STRIDE + k0));
#pragma unroll
            for (int np = 0; np < 4; np++)
                ldsm4(b[2 * np][0], b[2 * np][1], b[2 * np + 1][0], b[2 * np + 1][1],
                      sBu + 2u * (b_row + np * 16 * S_STRIDE + k0));
#pragma unroll
            for (int mt = 0; mt < 2; mt++)
#pragma unroll
                for (int nt = 0; nt < 8; nt++) {
                    asm volatile(
                        "mma.sync.aligned.m16n8k16.row.col.f32.f16.f16.f32 "
                        "{%0,%1,%2,%3},{%4,%5,%6,%7},{%8,%9},{%0,%1,%2,%3};"
                        : "+f"(c[mt][nt][0]), "+f"(c[mt][nt][1]),
                          "+f"(c[mt][nt][2]), "+f"(c[mt][nt][3])
                        : "r"(a[mt][0]), "r"(a[mt][1]), "r"(a[mt][2]), "r"(a[mt][3]),
                          "r"(b[nt][0]), "r"(b[nt][1]));
                }
        }
    }

    float* Cf = (float*)Cv;
    __half* Ch = (__half*)Cv;
#pragma unroll
    for (int mt = 0; mt < 2; mt++) {
        const int r0 = bm + wm + mt * 16 + g;
#pragma unroll
        for (int nt = 0; nt < 8; nt++) {
            const int col = bn + wn + nt * 8 + tg * 2;
            const float b0 = bias[col], b1 = bias[col + 1];
            float v0 = c[mt][nt][0] + b0, v1 = c[mt][nt][1] + b1;
            float v2 = c[mt][nt][2] + b0, v3 = c[mt][nt][3] + b1;
            if (mode == 2) {
                v0 = fmaxf(v0, 0.f); v1 = fmaxf(v1, 0.f);
                v2 = fmaxf(v2, 0.f); v3 = fmaxf(v3, 0.f);
            }
            if (mode >= 1) {
                *(__half2*)&Ch[(long)r0 * N + col]       = __floats2half2_rn(v0, v1);
                *(__half2*)&Ch[(long)(r0 + 8) * N + col] = __floats2half2_rn(v2, v3);
            } else {
                *(float2*)&Cf[(long)r0 * N + col]       = make_float2(v0, v1);
                *(float2*)&Cf[(long)(r0 + 8) * N + col] = make_float2(v2, v3);
            }
        }
    }
}

// ---------------- window-3 attention: one warp per (b,l), all 16 heads ------------
__global__ __launch_bounds__(128)
void attn_kernel(const __half* __restrict__ qkv,
                 const unsigned char* __restrict__ mask,
                 __half* __restrict__ ctx) {
    const int wg   = (blockIdx.x * blockDim.x + threadIdx.x) >> 5;  // = b*L + l
    const int lane = threadIdx.x & 31;
    const int l = wg & (LL - 1);
    const int b = wg >> 12;

    uint4 qv[4];
    const uint4* qp = (const uint4*)(qkv + (long)wg * 3072 + lane * 32);
#pragma unroll
    for (int i = 0; i < 4; i++) qv[i] = qp[i];
    float qf[32];
#pragma unroll
    for (int i = 0; i < 4; i++) {
        const __half2* h = (const __half2*)&qv[i];
#pragma unroll
        for (int j = 0; j < 4; j++) {
            float2 f = __half22float2(h[j]);
            qf[i * 8 + 2 * j]     = f.x;
            qf[i * 8 + 2 * j + 1] = f.y;
        }
    }

    float s[3];
    bool allow[3];
    int krow[3];
#pragma unroll
    for (int w = 0; w < 3; w++) {
        int idx = l - 1 + w;
        bool valid = (idx >= 0) && (idx < LL);
        int idxc = min(max(idx, 0), LL - 1);
        krow[w] = (b << 12) + idxc;
        const uint4* kp = (const uint4*)(qkv + (long)krow[w] * 3072 + 1024 + lane * 32);
        float a0 = 0.f, a1 = 0.f;
#pragma unroll
        for (int i = 0; i < 4; i++) {
            uint4 kvv = kp[i];
            const __half2* h = (const __half2*)&kvv;
#pragma unroll
            for (int j = 0; j < 4; j++) {
                float2 f = __half22float2(h[j]);
                a0 = fmaf(qf[i * 8 + 2 * j],     f.x, a0);
                a1 = fmaf(qf[i * 8 + 2 * j + 1], f.y, a1);
            }
        }
        float sv = a0 + a1;
        sv += __shfl_xor_sync(0xffffffffu, sv, 1);
        s[w] = sv;
        allow[w] = valid && (mask[krow[w]] == 0);
    }

#pragma unroll
    for (int w = 0; w < 3; w++) s[w] = allow[w] ? s[w] * 0.125f : -1e30f;
    float m = fmaxf(s[0], fmaxf(s[1], s[2]));
    float e0 = __expf(s[0] - m), e1 = __expf(s[1] - m), e2 = __expf(s[2] - m);
    float inv = 1.f / (e0 + e1 + e2);
    __half2 p[3];
    p[0] = __float2half2_rn(e0 * inv);
    p[1] = __float2half2_rn(e1 * inv);
    p[2] = __float2half2_rn(e2 * inv);

    __half2 o[16];
#pragma unroll
    for (int i = 0; i < 16; i++) o[i] = __float2half2_rn(0.f);
#pragma unroll
    for (int w = 0; w < 3; w++) {
        const uint4* vp = (const uint4*)(qkv + (long)krow[w] * 3072 + 2048 + lane * 32);
#pragma unroll
        for (int i = 0; i < 4; i++) {
            uint4 vv = vp[i];
            const __half2* h = (const __half2*)&vv;
#pragma unroll
            for (int j = 0; j < 4; j++)
                o[i * 4 + j] = __hfma2(p[w], h[j], o[i * 4 + j]);
        }
    }

    uint4* op = (uint4*)(ctx + (long)wg * 1024 + lane * 32);
#pragma unroll
    for (int i = 0; i < 4; i++) {
        uint4 v;
        v.x = *(unsigned*)&o[i * 4 + 0];
        v.y = *(unsigned*)&o[i * 4 + 1];
        v.z = *(unsigned*)&o[i * 4 + 2];
        v.w = *(unsigned*)&o[i * 4 + 3];
        op[i] = v;
    }
}

// ---------------- residual + layernorm: both inputs fp16 ----------------
template <int OUTH>
__global__ void resln_kernel(const __half* __restrict__ Xr, const __half* __restrict__ Yr,
                             const float* __restrict__ gamma, const float* __restrict__ beta,
                             void* __restrict__ outv) {
    const int row = blockIdx.x;
    const int tid = threadIdx.x;
    const int lane = tid & 31, warp = tid >> 5;

    __half2 xh0 = ((const __half2*)(Xr + (long)row * 1024))[2 * tid];
    __half2 xh1 = ((const __half2*)(Xr + (long)row * 1024))[2 * tid + 1];
    __half2 yh0 = ((const __half2*)(Yr + (long)row * 1024))[2 * tid];
    __half2 yh1 = ((const __half2*)(Yr + (long)row * 1024))[2 * tid + 1];
    float2 x0 = __half22float2(xh0), x1 = __half22float2(xh1);
    float2 y0 = __half22float2(yh0), y1 = __half22float2(yh1);
    float v0 = x0.x + y0.x, v1 = x0.y + y0.y, v2 = x1.x + y1.x, v3 = x1.y + y1.y;
    float s  = v0 + v1 + v2 + v3;
    float ss = v0 * v0 + v1 * v1 + v2 * v2 + v3 * v3;
#pragma unroll
    for (int off = 16; off; off >>= 1) {
        s  += __shfl_xor_sync(0xffffffffu, s, off);
        ss += __shfl_xor_sync(0xffffffffu, ss, off);
    }
    __shared__ float rs[8], rss[8];
    __shared__ float mean_s, rstd_s;
    if (lane == 0) { rs[warp] = s; rss[warp] = ss; }
    __syncthreads();
    if (tid == 0) {
        float S = 0.f, SS = 0.f;
#pragma unroll
        for (int i = 0; i < 8; i++) { S += rs[i]; SS += rss[i]; }
        float m = S * (1.f / 1024.f);
        float var = SS * (1.f / 1024.f) - m * m;
        mean_s = m;
        rstd_s = rsqrtf(var + 1e-5f);
    }
    __syncthreads();
    const float m = mean_s, r = rstd_s;
    float4 gm = ((const float4*)gamma)[tid];
    float4 bt = ((const float4*)beta)[tid];
    float o0 = (v0 - m) * r * gm.x + bt.x;
    float o1 = (v1 - m) * r * gm.y + bt.y;
    float o2 = (v2 - m) * r * gm.z + bt.z;
    float o3 = (v3 - m) * r * gm.w + bt.w;
    if (OUTH) {
        __half* out = (__half*)outv;
        ((__half2*)(out + (long)row * 1024))[2 * tid]     = __floats2half2_rn(o0, o1);
        ((__half2*)(out + (long)row * 1024))[2 * tid + 1] = __floats2half2_rn(o2, o3);
    } else {
        float* out = (float*)outv;
        ((float4*)(out + (long)row * 1024))[tid] = make_float4(o0, o1, o2, o3);
    }
}

// ---------------- launch ----------------
extern "C" void kernel_launch(void* const* d_in, const int* in_sizes, int n_in,
                              void* d_out, int out_size) {
    const float* X  = (const float*)d_in[0];
    const unsigned char* mask = (const unsigned char*)d_in[1];
    const float* pe = (const float*)d_in[2];
    const float* Wq = (const float*)d_in[3];
    const float* Wk = (const float*)d_in[4];
    const float* Wv = (const float*)d_in[5];
    const float* bq = (const float*)d_in[6];
    const float* bk = (const float*)d_in[7];
    const float* bv = (const float*)d_in[8];
    const float* Wo = (const float*)d_in[9];
    const float* bo = (const float*)d_in[10];
    const float* g1 = (const float*)d_in[11];
    const float* be1 = (const float*)d_in[12];
    const float* W1 = (const float*)d_in[13];
    const float* b1 = (const float*)d_in[14];
    const float* W2 = (const float*)d_in[15];
    const float* b2 = (const float*)d_in[16];
    const float* g2 = (const float*)d_in[17];
    const float* be2 = (const float*)d_in[18];
    float* out = (float*)d_out;

    void *pXp, *pqkv, *pctx, *pT, *pY, *pHb, *pZ, *pWqkv, *pbqkv, *pWo, *pW1, *pW2, *pPad;
    cudaGetSymbolAddress(&pXp, g_Xp);
    cudaGetSymbolAddress(&pqkv, g_qkv);
    cudaGetSymbolAddress(&pctx, g_ctx);
    cudaGetSymbolAddress(&pT, g_T);
    cudaGetSymbolAddress(&pY, g_Y);
    cudaGetSymbolAddress(&pHb, g_Hb);
    cudaGetSymbolAddress(&pZ, g_Z);
    cudaGetSymbolAddress(&pWqkv, g_Wqkv);
    cudaGetSymbolAddress(&pbqkv, g_bqkv);
    cudaGetSymbolAddress(&pWo, g_Wo);
    cudaGetSymbolAddress(&pW1, g_W1);
    cudaGetSymbolAddress(&pW2, g_W2);
    cudaGetSymbolAddress(&pPad, g_pad);
    __half* Xp   = (__half*)pXp;   __half* qkv  = (__half*)pqkv;
    __half* ctx  = (__half*)pctx;  __half* T    = (__half*)pT;
    __half* Y    = (__half*)pY;    __half* Hb   = (__half*)pHb;
    __half* Z    = (__half*)pZ;    __half* Wqkv = (__half*)pWqkv;
    float*  bqkv = (float*)pbqkv;  __half* WoT  = (__half*)pWo;
    __half* W1T  = (__half*)pW1;   __half* W2T  = (__half*)pW2;

    cudaFuncSetAttribute(gemm_fp16<32>,  cudaFuncAttributeMaxDynamicSharedMemorySize, GEMM_SMEM);
    cudaFuncSetAttribute(gemm_fp16<128>, cudaFuncAttributeMaxDynamicSharedMemorySize, GEMM_SMEM);

    // 1. prep X+pe
    prep_kernel<<<32768, 256>>>(X, pe, Xp);
    // 2. all weight transposes + bias pack
    prep_weights<<<12300, dim3(32, 8)>>>(Wq, Wk, Wv, Wo, W1, W2, bq, bk, bv,
                                         Wqkv, WoT, W1T, W2T, bqkv);
    // 3. dummy (aligns QKV GEMM into the profiled launch slot)
    dummy_kernel<<<1, 32>>>((float*)pPad);

    // 4. QKV projection  [32768,1024] x [1024,3072]
    gemm_fp16<32><<<dim3(24, 256), 256, GEMM_SMEM>>>(Xp, Wqkv, bqkv, qkv, MM, 3072, 1);

    // 5. window-3 attention (warp per (b,l))
    attn_kernel<<<8192, 128>>>(qkv, mask, ctx);

    // 6. O projection -> T (fp16)
    gemm_fp16<32><<<dim3(8, 256), 256, GEMM_SMEM>>>(ctx, WoT, bo, T, MM, 1024, 1);

    // 7. LN1(Xp + T) -> Y (fp16)
    resln_kernel<1><<<32768, 256>>>(Xp, T, g1, be1, Y);

    // 8. FFN1: relu(Y @ W1 + b1) -> Hb (fp16)
    gemm_fp16<32><<<dim3(32, 256), 256, GEMM_SMEM>>>(Y, W1T, b1, Hb, MM, 4096, 2);

    // 9. FFN2: Hb @ W2 + b2 -> Z (fp16)
    gemm_fp16<128><<<dim3(8, 256), 256, GEMM_SMEM>>>(Hb, W2T, b2, Z, MM, 1024, 1);

    // 10. LN2(Y + Z) -> out (fp32)
    resln_kernel<0><<<32768, 256>>>(Y, Z, g2, be2, out);
}

// round 14
// speedup vs baseline: 1.2888x; 1.1288x over previous
#include <cuda_runtime.h>
#include <cuda_fp16.h>
#include <cstdint>

// ---------------- problem constants ----------------
static constexpr int BB  = 8;
static constexpr int LL  = 4096;
static constexpr int HH  = 16;
static constexpr int DHD = 64;
static constexpr int MM  = BB * LL;       // 32768 rows

// ---------------- scratch (device globals; no allocation allowed) ----------------
__device__ __half g_Xp  [33554432];   // MM*1024 : X + pe (fp16)
__device__ __half g_qkv [100663296];  // MM*3072 : packed q|k|v (fp16)
__device__ __half g_ctx [33554432];   // MM*1024 : attention context (fp16)
__device__ __half g_T   [33554432];   // MM*1024 : O-proj output (fp16)
__device__ __half g_Y   [33554432];   // MM*1024 : LN1 output (fp16)
__device__ __half g_Hb  [134217728];  // MM*4096 : relu(FFN1) (fp16)
__device__ __half g_Z   [33554432];   // MM*1024 : FFN2 output (fp16)
__device__ __half g_Wqkv[3145728];    // [3072][1024]  transposed q|k|v weights
__device__ float  g_bqkv[3072];
__device__ __half g_Wo  [1048576];    // [1024][1024]  transposed
__device__ __half g_W1  [4194304];    // [4096][1024]  transposed
__device__ __half g_W2  [4194304];    // [1024][4096]  transposed
__device__ float  g_pad [32];         // dummy-kernel target

// ---------------- helpers ----------------
__device__ __forceinline__ unsigned smem_u32(const void* p) {
    return (unsigned)__cvta_generic_to_shared(p);
}
__device__ __forceinline__ void cp16(unsigned s, const void* g) {
    asm volatile("cp.async.cg.shared.global [%0], [%1], 16;" :: "r"(s), "l"(g));
}
__device__ __forceinline__ void cp_commit() { asm volatile("cp.async.commit_group;"); }
__device__ __forceinline__ void cp_wait3()  { asm volatile("cp.async.wait_group 3;"); }
__device__ __forceinline__ void ldsm4(unsigned& r0, unsigned& r1, unsigned& r2, unsigned& r3,
                                      unsigned addr) {
    asm volatile("ldmatrix.sync.aligned.m8n8.x4.shared.b16 {%0,%1,%2,%3}, [%4];"
                 : "=r"(r0), "=r"(r1), "=r"(r2), "=r"(r3) : "r"(addr));
}

// ---------------- prep: Xp = fp16(X + pe) ----------------
__global__ void prep_kernel(const float* __restrict__ X, const float* __restrict__ pe,
                            __half* __restrict__ Xp) {
    long i = ((long)blockIdx.x * blockDim.x + threadIdx.x) * 4;
    float4 x = *(const float4*)(X + i);
    long pi = i & (4194304L - 1);
    float4 p = *(const float4*)(pe + pi);
    __half2 h0 = __floats2half2_rn(x.x + p.x, x.y + p.y);
    __half2 h1 = __floats2half2_rn(x.z + p.z, x.w + p.w);
    *(__half2*)(Xp + i)     = h0;
    *(__half2*)(Xp + i + 2) = h1;
}

// ---------------- dummy (slot alignment so ncu profiles the QKV GEMM) -------------
__global__ void dummy_kernel(float* __restrict__ p) {
    if (threadIdx.x == 0) p[blockIdx.x] = 0.f;
}

// ---------------- fused weight prep: 6 transposes + bias pack in one launch -------
__device__ __forceinline__ void transpose_tile(const float* __restrict__ src,
                                               __half* __restrict__ dst,
                                               int K, int N, int tx, int ty,
                                               int x, int y) {
    __shared__ float t[32][33];
    const int n0 = tx * 32, k0 = ty * 32;
#pragma unroll
    for (int j = 0; j < 32; j += 8)
        t[y + j][x] = src[(long)(k0 + y + j) * N + n0 + x];
    __syncthreads();
#pragma unroll
    for (int j = 0; j < 32; j += 8)
        dst[(long)(n0 + y + j) * K + k0 + x] = __float2half_rn(t[x][y + j]);
}

__global__ void prep_weights(const float* __restrict__ Wq, const float* __restrict__ Wk,
                             const float* __restrict__ Wv, const float* __restrict__ Wo,
                             const float* __restrict__ W1, const float* __restrict__ W2,
                             const float* __restrict__ bq, const float* __restrict__ bk,
                             const float* __restrict__ bv,
                             __half* __restrict__ Wqkv, __half* __restrict__ WoT,
                             __half* __restrict__ W1T, __half* __restrict__ W2T,
                             float* __restrict__ bqkv) {
    const int id = blockIdx.x;
    const int x = threadIdx.x, y = threadIdx.y;
    if (id < 1024) {
        transpose_tile(Wq, Wqkv + 0, 1024, 1024, id & 31, id >> 5, x, y);
    } else if (id < 2048) {
        transpose_tile(Wk, Wqkv + 1048576, 1024, 1024, (id - 1024) & 31, (id - 1024) >> 5, x, y);
    } else if (id < 3072) {
        transpose_tile(Wv, Wqkv + 2097152, 1024, 1024, (id - 2048) & 31, (id - 2048) >> 5, x, y);
    } else if (id < 4096) {
        transpose_tile(Wo, WoT, 1024, 1024, (id - 3072) & 31, (id - 3072) >> 5, x, y);
    } else if (id < 8192) {
        int l = id - 4096;
        transpose_tile(W1, W1T, 1024, 4096, l & 127, l >> 7, x, y);
    } else if (id < 12288) {
        int l = id - 8192;
        transpose_tile(W2, W2T, 4096, 1024, l & 31, l >> 5, x, y);
    } else {
        int i = (id - 12288) * 256 + y * 32 + x;
        const float* src = (i < 1024) ? bq : ((i < 2048) ? bk : bv);
        bqkv[i] = src[i & 1023];
    }
}

// ---------------- GEMM: fp16 mma.sync m16n8k16 + ldmatrix ----------------
// 128x128x32 CTA tile, 4 warps each 64x64, 5-stage cp.async (wait_group 3), 2 CTA/SM
static constexpr int GBM = 128, GBN = 128, GBK = 32, STAGES = 5;
static constexpr int S_STRIDE = 40;                  // halves; 80B row (conflict-free)
static constexpr int SA_SIZE = GBM * S_STRIDE;
static constexpr int SB_SIZE = GBN * S_STRIDE;
static constexpr int STG_SIZE = SA_SIZE + SB_SIZE;   // 10240 halves = 20480 B
static constexpr int GEMM_SMEM = STAGES * STG_SIZE * 2;   // 102400 B

// mode: 0 = fp32 store, 1 = fp16 store, 2 = relu + fp16 store
template <int KT>
__global__ __launch_bounds__(128, 2)
void gemm_fp16(const __half* __restrict__ A, const __half* __restrict__ Bt,
               const float* __restrict__ bias, void* __restrict__ Cv,
               int M, int N, int mode) {
    constexpr int K = KT * GBK;
    extern __shared__ __half smem[];
    const int tid  = threadIdx.x;
    const int bm   = blockIdx.y * GBM, bn = blockIdx.x * GBN;
    const int warp = tid >> 5, lane = tid & 31;
    const int wm   = (warp >> 1) * 64, wn = (warp & 1) * 64;
    const int g    = lane >> 2, tg = lane & 3;

    const int a_row = (wm + (lane & 15)) * S_STRIDE + (lane >> 4) * 8;
    const int b_row = (wn + ((lane >> 4) & 1) * 8 + (lane & 7)) * S_STRIDE
                    + ((lane >> 3) & 1) * 8;

    float c[4][8][4];
#pragma unroll
    for (int mt = 0; mt < 4; mt++)
#pragma unroll
        for (int nt = 0; nt < 8; nt++)
#pragma unroll
            for (int j = 0; j < 4; j++) c[mt][nt][j] = 0.f;

    auto load_stage = [&](int stg, int kt) {
        __half* sA = smem + stg * STG_SIZE;
        __half* sB = sA + SA_SIZE;
        const __half* Ag = A + (long)bm * K + (long)kt * GBK;
        const __half* Bg = Bt + (long)bn * K + (long)kt * GBK;
#pragma unroll
        for (int i = 0; i < 4; i++) {
            int idx = i * 128 + tid;          // 0..511
            int row = idx >> 2;               // 0..127
            int cb  = (idx & 3) * 8;          // 0,8,16,24 halves
            cp16(smem_u32(sA + row * S_STRIDE + cb), Ag + (long)row * K + cb);
        }
#pragma unroll
        for (int i = 0; i < 4; i++) {
            int idx = i * 128 + tid;
            int row = idx >> 2;
            int cb  = (idx & 3) * 8;
            cp16(smem_u32(sB + row * S_STRIDE + cb), Bg + (long)row * K + cb);
        }
        cp_commit();
    };

    // prologue: fill 4 of 5 stages
    load_stage(0, 0);
    load_stage(1, 1);
    load_stage(2, 2);
    load_stage(3, 3);

#pragma unroll 1
    for (int kt = 0; kt < KT; kt++) {
        cp_wait3();          // oldest outstanding group (stage for kt) complete
        __syncthreads();
        // write slot (kt+4)%5 == (kt-1)%5, freed by the barrier above
        if (kt + 4 < KT) load_stage((kt + 4) % STAGES, kt + 4);
        else             cp_commit();

        const unsigned sAu = smem_u32(smem + (kt % STAGES) * STG_SIZE);
        const unsigned sBu = sAu + SA_SIZE * 2;
#pragma unroll
        for (int kk = 0; kk < 2; kk++) {
            const int k0 = kk * 16;
            unsigned a[4][4], b[8][2];
#pragma unroll
            for (int mt = 0; mt < 4; mt++)
                ldsm4(a[mt][0], a[mt][1], a[mt][2], a[mt][3],
                      sAu + 2u * (a_row + mt * 16 * S_STRIDE + k0));
#pragma unroll
            for (int np = 0; np < 4; np++)
                ldsm4(b[2 * np][0], b[2 * np][1], b[2 * np + 1][0], b[2 * np + 1][1],
                      sBu + 2u * (b_row + np * 16 * S_STRIDE + k0));
#pragma unroll
            for (int mt = 0; mt < 4; mt++)
#pragma unroll
                for (int nt = 0; nt < 8; nt++) {
                    asm volatile(
                        "mma.sync.aligned.m16n8k16.row.col.f32.f16.f16.f32 "
                        "{%0,%1,%2,%3},{%4,%5,%6,%7},{%8,%9},{%0,%1,%2,%3};"
                        : "+f"(c[mt][nt][0]), "+f"(c[mt][nt][1]),
                          "+f"(c[mt][nt][2]), "+f"(c[mt][nt][3])
                        : "r"(a[mt][0]), "r"(a[mt][1]), "r"(a[mt][2]), "r"(a[mt][3]),
                          "r"(b[nt][0]), "r"(b[nt][1]));
                }
        }
    }

    float* Cf = (float*)Cv;
    __half* Ch = (__half*)Cv;
#pragma unroll
    for (int mt = 0; mt < 4; mt++) {
        const int r0 = bm + wm + mt * 16 + g;
#pragma unroll
        for (int nt = 0; nt < 8; nt++) {
            const int col = bn + wn + nt * 8 + tg * 2;
            const float b0 = bias[col], b1 = bias[col + 1];
            float v0 = c[mt][nt][0] + b0, v1 = c[mt][nt][1] + b1;
            float v2 = c[mt][nt][2] + b0, v3 = c[mt][nt][3] + b1;
            if (mode == 2) {
                v0 = fmaxf(v0, 0.f); v1 = fmaxf(v1, 0.f);
                v2 = fmaxf(v2, 0.f); v3 = fmaxf(v3, 0.f);
            }
            if (mode >= 1) {
                *(__half2*)&Ch[(long)r0 * N + col]       = __floats2half2_rn(v0, v1);
                *(__half2*)&Ch[(long)(r0 + 8) * N + col] = __floats2half2_rn(v2, v3);
            } else {
                *(float2*)&Cf[(long)r0 * N + col]       = make_float2(v0, v1);
                *(float2*)&Cf[(long)(r0 + 8) * N + col] = make_float2(v2, v3);
            }
        }
    }
}

// ---------------- window-3 attention: one warp per (b,l), all 16 heads ------------
__global__ __launch_bounds__(128)
void attn_kernel(const __half* __restrict__ qkv,
                 const unsigned char* __restrict__ mask,
                 __half* __restrict__ ctx) {
    const int wg   = (blockIdx.x * blockDim.x + threadIdx.x) >> 5;  // = b*L + l
    const int lane = threadIdx.x & 31;
    const int l = wg & (LL - 1);
    const int b = wg >> 12;

    uint4 qv[4];
    const uint4* qp = (const uint4*)(qkv + (long)wg * 3072 + lane * 32);
#pragma unroll
    for (int i = 0; i < 4; i++) qv[i] = qp[i];
    float qf[32];
#pragma unroll
    for (int i = 0; i < 4; i++) {
        const __half2* h = (const __half2*)&qv[i];
#pragma unroll
        for (int j = 0; j < 4; j++) {
            float2 f = __half22float2(h[j]);
            qf[i * 8 + 2 * j]     = f.x;
            qf[i * 8 + 2 * j + 1] = f.y;
        }
    }

    float s[3];
    bool allow[3];
    int krow[3];
#pragma unroll
    for (int w = 0; w < 3; w++) {
        int idx = l - 1 + w;
        bool valid = (idx >= 0) && (idx < LL);
        int idxc = min(max(idx, 0), LL - 1);
        krow[w] = (b << 12) + idxc;
        const uint4* kp = (const uint4*)(qkv + (long)krow[w] * 3072 + 1024 + lane * 32);
        float a0 = 0.f, a1 = 0.f;
#pragma unroll
        for (int i = 0; i < 4; i++) {
            uint4 kvv = kp[i];
            const __half2* h = (const __half2*)&kvv;
#pragma unroll
            for (int j = 0; j < 4; j++) {
                float2 f = __half22float2(h[j]);
                a0 = fmaf(qf[i * 8 + 2 * j],     f.x, a0);
                a1 = fmaf(qf[i * 8 + 2 * j + 1], f.y, a1);
            }
        }
        float sv = a0 + a1;
        sv += __shfl_xor_sync(0xffffffffu, sv, 1);
        s[w] = sv;
        allow[w] = valid && (mask[krow[w]] == 0);
    }

#pragma unroll
    for (int w = 0; w < 3; w++) s[w] = allow[w] ? s[w] * 0.125f : -1e30f;
    float m = fmaxf(s[0], fmaxf(s[1], s[2]));
    float e0 = __expf(s[0] - m), e1 = __expf(s[1] - m), e2 = __expf(s[2] - m);
    float inv = 1.f / (e0 + e1 + e2);
    __half2 p[3];
    p[0] = __float2half2_rn(e0 * inv);
    p[1] = __float2half2_rn(e1 * inv);
    p[2] = __float2half2_rn(e2 * inv);

    __half2 o[16];
#pragma unroll
    for (int i = 0; i < 16; i++) o[i] = __float2half2_rn(0.f);
#pragma unroll
    for (int w = 0; w < 3; w++) {
        const uint4* vp = (const uint4*)(qkv + (long)krow[w] * 3072 + 2048 + lane * 32);
#pragma unroll
        for (int i = 0; i < 4; i++) {
            uint4 vv = vp[i];
            const __half2* h = (const __half2*)&vv;
#pragma unroll
            for (int j = 0; j < 4; j++)
                o[i * 4 + j] = __hfma2(p[w], h[j], o[i * 4 + j]);
        }
    }

    uint4* op = (uint4*)(ctx + (long)wg * 1024 + lane * 32);
#pragma unroll
    for (int i = 0; i < 4; i++) {
        uint4 v;
        v.x = *(unsigned*)&o[i * 4 + 0];
        v.y = *(unsigned*)&o[i * 4 + 1];
        v.z = *(unsigned*)&o[i * 4 + 2];
        v.w = *(unsigned*)&o[i * 4 + 3];
        op[i] = v;
    }
}

// ---------------- residual + layernorm: both inputs fp16 ----------------
template <int OUTH>
__global__ void resln_kernel(const __half* __restrict__ Xr, const __half* __restrict__ Yr,
                             const float* __restrict__ gamma, const float* __restrict__ beta,
                             void* __restrict__ outv) {
    const int row = blockIdx.x;
    const int tid = threadIdx.x;
    const int lane = tid & 31, warp = tid >> 5;

    __half2 xh0 = ((const __half2*)(Xr + (long)row * 1024))[2 * tid];
    __half2 xh1 = ((const __half2*)(Xr + (long)row * 1024))[2 * tid + 1];
    __half2 yh0 = ((const __half2*)(Yr + (long)row * 1024))[2 * tid];
    __half2 yh1 = ((const __half2*)(Yr + (long)row * 1024))[2 * tid + 1];
    float2 x0 = __half22float2(xh0), x1 = __half22float2(xh1);
    float2 y0 = __half22float2(yh0), y1 = __half22float2(yh1);
    float v0 = x0.x + y0.x, v1 = x0.y + y0.y, v2 = x1.x + y1.x, v3 = x1.y + y1.y;
    float s  = v0 + v1 + v2 + v3;
    float ss = v0 * v0 + v1 * v1 + v2 * v2 + v3 * v3;
#pragma unroll
    for (int off = 16; off; off >>= 1) {
        s  += __shfl_xor_sync(0xffffffffu, s, off);
        ss += __shfl_xor_sync(0xffffffffu, ss, off);
    }
    __shared__ float rs[8], rss[8];
    __shared__ float mean_s, rstd_s;
    if (lane == 0) { rs[warp] = s; rss[warp] = ss; }
    __syncthreads();
    if (tid == 0) {
        float S = 0.f, SS = 0.f;
#pragma unroll
        for (int i = 0; i < 8; i++) { S += rs[i]; SS += rss[i]; }
        float m = S * (1.f / 1024.f);
        float var = SS * (1.f / 1024.f) - m * m;
        mean_s = m;
        rstd_s = rsqrtf(var + 1e-5f);
    }
    __syncthreads();
    const float m = mean_s, r = rstd_s;
    float4 gm = ((const float4*)gamma)[tid];
    float4 bt = ((const float4*)beta)[tid];
    float o0 = (v0 - m) * r * gm.x + bt.x;
    float o1 = (v1 - m) * r * gm.y + bt.y;
    float o2 = (v2 - m) * r * gm.z + bt.z;
    float o3 = (v3 - m) * r * gm.w + bt.w;
    if (OUTH) {
        __half* out = (__half*)outv;
        ((__half2*)(out + (long)row * 1024))[2 * tid]     = __floats2half2_rn(o0, o1);
        ((__half2*)(out + (long)row * 1024))[2 * tid + 1] = __floats2half2_rn(o2, o3);
    } else {
        float* out = (float*)outv;
        ((float4*)(out + (long)row * 1024))[tid] = make_float4(o0, o1, o2, o3);
    }
}

// ---------------- launch ----------------
extern "C" void kernel_launch(void* const* d_in, const int* in_sizes, int n_in,
                              void* d_out, int out_size) {
    const float* X  = (const float*)d_in[0];
    const unsigned char* mask = (const unsigned char*)d_in[1];
    const float* pe = (const float*)d_in[2];
    const float* Wq = (const float*)d_in[3];
    const float* Wk = (const float*)d_in[4];
    const float* Wv = (const float*)d_in[5];
    const float* bq = (const float*)d_in[6];
    const float* bk = (const float*)d_in[7];
    const float* bv = (const float*)d_in[8];
    const float* Wo = (const float*)d_in[9];
    const float* bo = (const float*)d_in[10];
    const float* g1 = (const float*)d_in[11];
    const float* be1 = (const float*)d_in[12];
    const float* W1 = (const float*)d_in[13];
    const float* b1 = (const float*)d_in[14];
    const float* W2 = (const float*)d_in[15];
    const float* b2 = (const float*)d_in[16];
    const float* g2 = (const float*)d_in[17];
    const float* be2 = (const float*)d_in[18];
    float* out = (float*)d_out;

    void *pXp, *pqkv, *pctx, *pT, *pY, *pHb, *pZ, *pWqkv, *pbqkv, *pWo, *pW1, *pW2, *pPad;
    cudaGetSymbolAddress(&pXp, g_Xp);
    cudaGetSymbolAddress(&pqkv, g_qkv);
    cudaGetSymbolAddress(&pctx, g_ctx);
    cudaGetSymbolAddress(&pT, g_T);
    cudaGetSymbolAddress(&pY, g_Y);
    cudaGetSymbolAddress(&pHb, g_Hb);
    cudaGetSymbolAddress(&pZ, g_Z);
    cudaGetSymbolAddress(&pWqkv, g_Wqkv);
    cudaGetSymbolAddress(&pbqkv, g_bqkv);
    cudaGetSymbolAddress(&pWo, g_Wo);
    cudaGetSymbolAddress(&pW1, g_W1);
    cudaGetSymbolAddress(&pW2, g_W2);
    cudaGetSymbolAddress(&pPad, g_pad);
    __half* Xp   = (__half*)pXp;   __half* qkv  = (__half*)pqkv;
    __half* ctx  = (__half*)pctx;  __half* T    = (__half*)pT;
    __half* Y    = (__half*)pY;    __half* Hb   = (__half*)pHb;
    __half* Z    = (__half*)pZ;    __half* Wqkv = (__half*)pWqkv;
    float*  bqkv = (float*)pbqkv;  __half* WoT  = (__half*)pWo;
    __half* W1T  = (__half*)pW1;   __half* W2T  = (__half*)pW2;

    cudaFuncSetAttribute(gemm_fp16<32>,  cudaFuncAttributeMaxDynamicSharedMemorySize, GEMM_SMEM);
    cudaFuncSetAttribute(gemm_fp16<128>, cudaFuncAttributeMaxDynamicSharedMemorySize, GEMM_SMEM);

    // 1. prep X+pe
    prep_kernel<<<32768, 256>>>(X, pe, Xp);
    // 2. all weight transposes + bias pack
    prep_weights<<<12300, dim3(32, 8)>>>(Wq, Wk, Wv, Wo, W1, W2, bq, bk, bv,
                                         Wqkv, WoT, W1T, W2T, bqkv);
    // 3. dummy (aligns QKV GEMM into the profiled launch slot)
    dummy_kernel<<<1, 32>>>((float*)pPad);

    // 4. QKV projection  [32768,1024] x [1024,3072]
    gemm_fp16<32><<<dim3(24, 256), 128, GEMM_SMEM>>>(Xp, Wqkv, bqkv, qkv, MM, 3072, 1);

    // 5. window-3 attention (warp per (b,l))
    attn_kernel<<<8192, 128>>>(qkv, mask, ctx);

    // 6. O projection -> T (fp16)
    gemm_fp16<32><<<dim3(8, 256), 128, GEMM_SMEM>>>(ctx, WoT, bo, T, MM, 1024, 1);

    // 7. LN1(Xp + T) -> Y (fp16)
    resln_kernel<1><<<32768, 256>>>(Xp, T, g1, be1, Y);

    // 8. FFN1: relu(Y @ W1 + b1) -> Hb (fp16)
    gemm_fp16<32><<<dim3(32, 256), 128, GEMM_SMEM>>>(Y, W1T, b1, Hb, MM, 4096, 2);

    // 9. FFN2: Hb @ W2 + b2 -> Z (fp16)
    gemm_fp16<128><<<dim3(8, 256), 128, GEMM_SMEM>>>(Hb, W2T, b2, Z, MM, 1024, 1);

    // 10. LN2(Y + Z) -> out (fp32)
    resln_kernel<0><<<32768, 256>>>(Y, Z, g2, be2, out);
}